// round 16
// baseline (speedup 1.0000x reference)
#include <cuda_runtime.h>
#include <cstdint>

#define NN      12000
#define HID     32
#define TSTEPS  50
#define TM      128
#define NBLK    94               // row blocks
#define CPB     375              // chunks per block (12000/32)
#define TOTCH   (NBLK * CPB)     // 35250 global chunks
#define GRID    296              // 148 SMs x occ 2, one full wave
#define BASE    119              // chunks per CTA (first 26 get 120)
#define REM     26               // TOTCH - 296*119
#define NSTAGES 5
#define STAGE_BYTES 20480        // A: 128*32*4 = 16384  +  B: 32*32*4 = 4096
#define SMEM_REQ (NSTAGES * STAGE_BYTES)

__device__ float g_suppT[HID * NN];            // support^T, tf32-rounded
__device__ float g_part[2 * GRID * TM * HID];  // 2 partial tiles per CTA

// closed-form range arithmetic shared by GEMM and reduce
__host__ __device__ __forceinline__ int range_start(int i) {
    return BASE * i + (i < REM ? i : REM);
}
__host__ __device__ __forceinline__ int range_end(int i) {
    return range_start(i) + BASE + (i < REM ? 1 : 0);
}

// ---------------------------------------------------------------------------
// Kernel 1: support = [z | a_t] @ W, transposed + tf32-rounded (round-5 exact)
// ---------------------------------------------------------------------------
__global__ void support_kernel(const float* __restrict__ t,
                               const float* __restrict__ z,
                               const float* __restrict__ treat,
                               const float* __restrict__ W) {
    __shared__ float Ws[33 * 32];
    __shared__ float S[32][33];
    int tid = threadIdx.x;
    for (int i = tid; i < 33 * 32; i += blockDim.x) Ws[i] = W[i];
    __syncthreads();

    int a_idx = (int)(t[0] * (float)(TSTEPS - 1));
    a_idx = min(max(a_idx, 0), TSTEPS - 1);

    int lane = tid & 31;
    int warp = tid >> 5;
    int row0 = blockIdx.x * 32;
    int r0   = warp * 4;

    float zv[4], acc[4];
#pragma unroll
    for (int j = 0; j < 4; j++) {
        int row = row0 + r0 + j;
        zv[j]  = z[row * 32 + lane];
        acc[j] = treat[row * TSTEPS + a_idx] * Ws[32 * 32 + lane];
    }
#pragma unroll
    for (int k = 0; k < 32; k++) {
        float w = Ws[k * 32 + lane];
#pragma unroll
        for (int j = 0; j < 4; j++) {
            float zk = __shfl_sync(0xffffffffu, zv[j], k);
            acc[j] = fmaf(zk, w, acc[j]);
        }
    }
#pragma unroll
    for (int j = 0; j < 4; j++) {
        uint32_t bits;
        asm("cvt.rna.tf32.f32 %0, %1;" : "=r"(bits) : "f"(acc[j]));
        S[r0 + j][lane] = __uint_as_float(bits);
    }
    __syncthreads();

#pragma unroll
    for (int j = 0; j < 4; j++) {
        int idx = tid + 256 * j;
        int col = idx >> 5;
        int r   = idx & 31;
        g_suppT[col * NN + row0 + r] = S[r][col];
    }
}

// ---------------------------------------------------------------------------
// Stage load for global chunk gch (round-5 line-complete lane maps).
// ---------------------------------------------------------------------------
__device__ __forceinline__ void load_stage(char* stage, const float* __restrict__ adj,
                                           int gch, int tid) {
    int blk  = gch / CPB;
    int row0 = blk * TM;
    int gk   = (gch - blk * CPB) * 32;

    int q  = tid & 7;
    int rb = tid >> 3;
    uint32_t sbase = (uint32_t)__cvta_generic_to_shared(stage);

#pragma unroll
    for (int i = 0; i < 4; i++) {
        int r = i * 32 + rb;
        const float* src = adj + (long long)(row0 + r) * NN + gk + q * 4;
        uint32_t dst = sbase + r * 128 + (uint32_t)((q ^ (r & 7)) << 4);
        int sz = (row0 + r < NN) ? 16 : 0;
        asm volatile("cp.async.cg.shared.global.L2::256B [%0], [%1], 16, %2;\n"
                     :: "r"(dst), "l"(src), "r"(sz));
    }
    {
        int c = rb;
        const float* src = g_suppT + (long long)c * NN + gk + q * 4;
        uint32_t dst = sbase + 16384 + c * 128 + (uint32_t)((q ^ (c & 7)) << 4);
        asm volatile("cp.async.cg.shared.global.L2::256B [%0], [%1], 16;\n"
                     :: "r"(dst), "l"(src));
    }
}

// ---------------------------------------------------------------------------
// Kernel 2: tf32 mma.sync GEMM over a balanced contiguous chunk range.
// ---------------------------------------------------------------------------
__global__ void __launch_bounds__(256, 2)
gemm_mma_kernel(const float* __restrict__ adj) {
    extern __shared__ char dsm[];
    int tid  = threadIdx.x;
    int warp = tid >> 5;
    int lane = tid & 31;
    int g    = lane >> 2;
    int tg   = tid & 3;

    int ci = blockIdx.x;
    int s  = range_start(ci);
    int e  = range_end(ci);
    int blk0 = s / CPB;

    float acc[4][4];
#pragma unroll
    for (int n = 0; n < 4; n++)
#pragma unroll
        for (int i = 0; i < 4; i++) acc[n][i] = 0.f;

    const uint32_t aoff = (uint32_t)(warp * 16 + g) * 128 + tg * 4;
    const uint32_t boff = 16384u + (uint32_t)g * 128 + tg * 4;

#pragma unroll
    for (int p = 0; p < NSTAGES - 1; p++) {
        load_stage(dsm + p * STAGE_BYTES, adj, s + p, tid);
        asm volatile("cp.async.commit_group;\n" ::: "memory");
    }

    for (int c = s; c < e; c++) {
        asm volatile("cp.async.wait_group %0;\n" :: "n"(NSTAGES - 2) : "memory");
        __syncthreads();

        if (c + NSTAGES - 1 < e)
            load_stage(dsm + ((c - s + NSTAGES - 1) % NSTAGES) * STAGE_BYTES,
                       adj, c + NSTAGES - 1, tid);
        asm volatile("cp.async.commit_group;\n" ::: "memory");

        const char* st = dsm + ((c - s) % NSTAGES) * STAGE_BYTES;
#pragma unroll
        for (int ks = 0; ks < 4; ks++) {
            uint32_t q0 = (uint32_t)(((2 * ks) ^ g) << 4);
            uint32_t q1 = (uint32_t)(((2 * ks + 1) ^ g) << 4);

            uint32_t a0 = *(const uint32_t*)(st + aoff + q0);
            uint32_t a2 = *(const uint32_t*)(st + aoff + q1);
            uint32_t a1 = *(const uint32_t*)(st + aoff + 1024 + q0);
            uint32_t a3 = *(const uint32_t*)(st + aoff + 1024 + q1);
#pragma unroll
            for (int nt = 0; nt < 4; nt++) {
                uint32_t b0 = *(const uint32_t*)(st + boff + nt * 1024 + q0);
                uint32_t b1 = *(const uint32_t*)(st + boff + nt * 1024 + q1);
                asm volatile(
                    "mma.sync.aligned.m16n8k8.row.col.f32.tf32.tf32.f32 "
                    "{%0,%1,%2,%3}, {%4,%5,%6,%7}, {%8,%9}, {%0,%1,%2,%3};\n"
                    : "+f"(acc[nt][0]), "+f"(acc[nt][1]),
                      "+f"(acc[nt][2]), "+f"(acc[nt][3])
                    : "r"(a0), "r"(a1), "r"(a2), "r"(a3), "r"(b0), "r"(b1));
            }
        }

        // flush at end of block or end of range (tile-local rows, no guard)
        int cn = c + 1;
        if (cn == e || cn - (cn / CPB) * CPB == 0) {
            int blk  = c / CPB;
            int slot = (blk == blk0) ? 0 : 1;
            float* part = g_part + ((long long)(2 * ci + slot)) * (TM * HID);
            int r_lo = warp * 16 + g;
            int r_hi = r_lo + 8;
#pragma unroll
            for (int nt = 0; nt < 4; nt++) {
                int colb = nt * 8 + 2 * tg;
                *(float2*)(part + r_lo * HID + colb) =
                    make_float2(acc[nt][0], acc[nt][1]);
                *(float2*)(part + r_hi * HID + colb) =
                    make_float2(acc[nt][2], acc[nt][3]);
#pragma unroll
                for (int i = 0; i < 4; i++) acc[nt][i] = 0.f;
            }
        }
    }
}

// ---------------------------------------------------------------------------
// Kernel 3: out = relu(sum of covering partial segments + b), ascending-i order
// ---------------------------------------------------------------------------
__global__ void reduce_relu_kernel(float* __restrict__ out,
                                   const float* __restrict__ bias) {
    int idx = blockIdx.x * 256 + threadIdx.x;   // float4 within block tiles
    if (idx >= NBLK * 1024) return;
    int b   = idx >> 10;
    int pos = idx & 1023;
    int r   = pos >> 3;
    int c4  = pos & 7;

    float4 sum = ((const float4*)bias)[c4];

    int lo = (CPB * b) / (BASE + 1) - 1; if (lo < 0) lo = 0;
    int hi = (CPB * (b + 1)) / BASE + 1; if (hi > GRID - 1) hi = GRID - 1;
    for (int i = lo; i <= hi; i++) {
        int s  = range_start(i);
        int e  = range_end(i);
        int bs = s / CPB;
        int be = (e - 1) / CPB;
        int slot = -1;
        if (bs == b) slot = 0;
        else if (bs == b - 1 && be == b) slot = 1;
        if (slot >= 0) {
            const float4* p = (const float4*)(g_part +
                ((long long)(2 * i + slot)) * (TM * HID));
            float4 v = p[pos];
            sum.x += v.x; sum.y += v.y; sum.z += v.z; sum.w += v.w;
        }
    }

    int row = b * TM + r;
    if (row < NN) {
        float4 o;
        o.x = fmaxf(sum.x, 0.f);
        o.y = fmaxf(sum.y, 0.f);
        o.z = fmaxf(sum.z, 0.f);
        o.w = fmaxf(sum.w, 0.f);
        ((float4*)out)[(long long)row * 8 + c4] = o;
    }
}

// ---------------------------------------------------------------------------
extern "C" void kernel_launch(void* const* d_in, const int* in_sizes, int n_in,
                              void* d_out, int out_size) {
    (void)in_sizes; (void)n_in; (void)out_size;
    const float* t     = (const float*)d_in[0];
    const float* z     = (const float*)d_in[1];
    const float* adj   = (const float*)d_in[2];
    const float* treat = (const float*)d_in[3];
    const float* W     = (const float*)d_in[4];
    const float* b     = (const float*)d_in[5];
    float* out = (float*)d_out;

    cudaFuncSetAttribute(gemm_mma_kernel,
                         cudaFuncAttributeMaxDynamicSharedMemorySize, SMEM_REQ);

    support_kernel<<<NN / 32, 256>>>(t, z, treat, W);
    gemm_mma_kernel<<<GRID, 256, SMEM_REQ>>>(adj);
    reduce_relu_kernel<<<(NBLK * 1024 + 255) / 256, 256>>>(out, b);
}